// round 17
// baseline (speedup 1.0000x reference)
#include <cuda_runtime.h>
#include <cuda_fp16.h>
#include <math.h>
#include <stdint.h>

#define Cn 512
#define Bn 64
#define Nn 1024
#define Mn 16
#define SCALE 0.04419417382415922f   // 512^-0.5

// ---------------- scratch (allocation-free) ----------------
__device__ float g_bqA [1024];
__device__ float g_bvo [512];
__device__ float g_L2  [64 * 16 * 1024];
__device__ float g_L1  [64 * 1024 * 16];
__device__ float g_AFo [1024 * 512];
__device__ __half g_xh   [(size_t)64 * 1024 * 512];
__device__ __half g_xph  [1024 * 512];
__device__ __half g_xpl  [1024 * 512];
__device__ __half g_aqkh [64 * 32 * 512];
__device__ __half g_aqkl [64 * 32 * 512];
__device__ __half g_WqTh [512 * 512];
__device__ __half g_WqTl [512 * 512];
__device__ __half g_WkTh [512 * 512];
__device__ __half g_WkTl [512 * 512];
__device__ __half g_WvTh [512 * 512];
__device__ __half g_WvTl [512 * 512];
__device__ __half g_Wqh  [512 * 512];
__device__ __half g_Wql  [512 * 512];
__device__ __half g_Woh  [512 * 512];
__device__ __half g_Wol  [512 * 512];
__device__ __half g_Ah   [1024 * 512];
__device__ __half g_Al   [1024 * 512];
__device__ __half g_Wch  [512 * 512];
__device__ __half g_Wcl  [512 * 512];
__device__ __half g_xah  [1024 * 512];
__device__ __half g_xal  [1024 * 512];

__device__ __forceinline__ uint32_t smem_u32(const void* p) {
    return (uint32_t)__cvta_generic_to_shared(p);
}
__device__ __forceinline__ void cp_async16(uint32_t s, const void* g) {
    asm volatile("cp.async.cg.shared.global [%0], [%1], 16;" :: "r"(s), "l"(g));
}
__device__ __forceinline__ void ldx4(uint32_t* r, uint32_t addr) {
    asm volatile("ldmatrix.sync.aligned.m8n8.x4.shared.b16 {%0,%1,%2,%3}, [%4];"
                 : "=r"(r[0]), "=r"(r[1]), "=r"(r[2]), "=r"(r[3]) : "r"(addr));
}
__device__ __forceinline__ void ldx2t(uint32_t* r, uint32_t addr) {
    asm volatile("ldmatrix.sync.aligned.m8n8.x2.trans.shared.b16 {%0,%1}, [%2];"
                 : "=r"(r[0]), "=r"(r[1]) : "r"(addr));
}
__device__ __forceinline__ void mma16816(float* c, const uint32_t* a, uint32_t b0, uint32_t b1) {
    asm volatile(
        "mma.sync.aligned.m16n8k16.row.col.f32.f16.f16.f32 "
        "{%0,%1,%2,%3}, {%4,%5,%6,%7}, {%8,%9}, {%0,%1,%2,%3};"
        : "+f"(c[0]), "+f"(c[1]), "+f"(c[2]), "+f"(c[3])
        : "r"(a[0]), "r"(a[1]), "r"(a[2]), "r"(a[3]), "r"(b0), "r"(b1));
}
__device__ __forceinline__ void split_store(__half* H, __half* Lo, size_t idx,
                                            float a, float b) {
    __half h0 = __float2half(a), h1 = __float2half(b);
    *(__half2*)(H + idx)  = __halves2half2(h0, h1);
    *(__half2*)(Lo + idx) = __halves2half2(__float2half(a - __half2float(h0)),
                                           __float2half(b - __half2float(h1)));
}

// ================= merged prep + split (one launch; independent work) =================
// blocks [0,1024): split x -> xh fp16 + pooled xp (fp16 h/l)        (512 threads)
// blocks [1024,2304): prep planes z = (bid-1024)>>8                 (256 threads)
//   z0: Wq->WqT h/l ; z1: Wk->WkT h/l ; z2: Wv->WvT h/l ;
//   z3: Wq->Wqh/l, Wo->Woh/l ; z4: bvo = Wo.bv
__global__ __launch_bounds__(512)
void prep_split_kernel(const float* __restrict__ x,
                       const float* __restrict__ Wq, const float* __restrict__ Wk,
                       const float* __restrict__ Wv, const float* __restrict__ Wo,
                       const float* __restrict__ bv,
                       __half* __restrict__ xh, __half* __restrict__ xph,
                       __half* __restrict__ xpl,
                       __half* __restrict__ WqTh, __half* __restrict__ WqTl,
                       __half* __restrict__ WkTh, __half* __restrict__ WkTl,
                       __half* __restrict__ WvTh, __half* __restrict__ WvTl,
                       __half* __restrict__ Wqh, __half* __restrict__ Wql,
                       __half* __restrict__ Woh, __half* __restrict__ Wol,
                       float* __restrict__ bvo)
{
    const int tid = threadIdx.x;
    if (blockIdx.x < 1024) {
        const int bm = blockIdx.x;
        const int c  = tid;
        const size_t ob = (size_t)bm * 64 * Cn + c;
        const float* base = x + ob;
        float s = 0.f;
#pragma unroll 4
        for (int t = 0; t < 64; t++) {
            float vv = base[(size_t)t * Cn];
            s += vv;
            xh[ob + (size_t)t * Cn] = __float2half(vv);
        }
        const float xv = s * (1.0f / 64.0f);
        __half h = __float2half(xv);
        xph[(size_t)bm * Cn + c] = h;
        xpl[(size_t)bm * Cn + c] = __float2half(xv - __half2float(h));
        return;
    }
    if (tid >= 256) return;
    const int id2 = blockIdx.x - 1024;
    const int z   = id2 >> 8;
    const int bid = id2 & 255;
    const int bx = bid & 15, by = bid >> 4;
    const int tx = tid & 31, ty = tid >> 5;

    if (z == 3) {
        const int gi = bid * 256 + tid;                  // float4 units
        float4 q = ((const float4*)Wq)[gi];
        float4 o = ((const float4*)Wo)[gi];
        const size_t d = (size_t)gi * 4;
        split_store(Wqh, Wql, d,     q.x, q.y);
        split_store(Wqh, Wql, d + 2, q.z, q.w);
        split_store(Woh, Wol, d,     o.x, o.y);
        split_store(Woh, Wol, d + 2, o.z, o.w);
        return;
    }
    if (z == 4) {
        if (bid < 64) {
            const int row  = bid * 8 + (tid >> 5);
            const int lane = tid & 31;
            const float* sr = Wo + (size_t)row * Cn;
            float s = 0.f;
#pragma unroll
            for (int k = 0; k < 16; k++) s += sr[lane + 32 * k] * __ldg(&bv[lane + 32 * k]);
#pragma unroll
            for (int off = 16; off > 0; off >>= 1) s += __shfl_xor_sync(0xffffffffu, s, off);
            if (lane == 0) bvo[row] = s;
        }
        return;
    }
    __shared__ float t[32][33];
    const float* s = (z == 0) ? Wq : (z == 1) ? Wk : Wv;
    const int gx = bx * 32 + tx;
    const int y0 = by * 32 + ty;
#pragma unroll
    for (int j = 0; j < 32; j += 8)
        t[ty + j][tx] = s[(size_t)(y0 + j) * Cn + gx];
    __syncthreads();
    __half *Dh, *Dl;
    if (z == 0)      { Dh = WqTh; Dl = WqTl; }
    else if (z == 1) { Dh = WkTh; Dl = WkTl; }
    else             { Dh = WvTh; Dl = WvTl; }
    const int ox  = by * 32 + tx;
    const int oy0 = bx * 32 + ty;
#pragma unroll
    for (int j = 0; j < 32; j += 8) {
        const float val = t[tx][ty + j];
        const size_t di = (size_t)(oy0 + j) * Cn + ox;
        __half h = __float2half(val);
        Dh[di] = h;
        Dl[di] = __float2half(val - __half2float(h));
    }
}

// ================= shared h/l-NT mma skeleton (3-stage, single sync) =================
#define HL_STAGE 49152
#define HL_SMEM (3 * HL_STAGE)

#define HL_LOAD(I, Ahg, Alg, Bhg, Blg, ROWBLK, N0)                                        \
    do {                                                                                  \
        const int s_ = (I) % 3; const int k0_ = (I) * 64;                                 \
        const uint32_t sb_ = sbase + s_ * HL_STAGE;                                       \
        {                                                                                 \
            const int row = t >> 1; const int cb = (t & 1) * 4;                           \
            const __half* gh = (Ahg) + (size_t)((ROWBLK) + row) * Cn + k0_ + cb * 8;      \
            const __half* gl = (Alg) + (size_t)((ROWBLK) + row) * Cn + k0_ + cb * 8;      \
            _Pragma("unroll")                                                             \
            for (int j = 0; j < 4; j++) {                                                 \
                uint32_t o = (uint32_t)(row * 128 + (cb + j) * 16) ^ ((uint32_t)(row & 7) << 4); \
                cp_async16(sb_ + o, gh + j * 8);                                          \
                cp_async16(sb_ + 16384 + o, gl + j * 8);                                  \
            }                                                                             \
        }                                                                                 \
        {                                                                                 \
            const int jr = t >> 2; const int ch = (t & 3) * 2;                            \
            const __half* gh = (Bhg) + (size_t)((N0) + jr) * Cn + k0_ + ch * 8;           \
            const __half* gl = (Blg) + (size_t)((N0) + jr) * Cn + k0_ + ch * 8;           \
            _Pragma("unroll")                                                             \
            for (int j = 0; j < 2; j++) {                                                 \
                uint32_t o = (uint32_t)(jr * 128 + (ch + j) * 16) ^ ((uint32_t)(jr & 7) << 4); \
                cp_async16(sb_ + 32768 + o, gh + j * 8);                                  \
                cp_async16(sb_ + 40960 + o, gl + j * 8);                                  \
            }                                                                             \
        }                                                                                 \
        asm volatile("cp.async.commit_group;" ::: "memory");                              \
    } while (0)

#define HL_MAINLOOP(Ahg, Alg, Bhg, Blg, ROWBLK, N0)                                       \
    HL_LOAD(0, Ahg, Alg, Bhg, Blg, ROWBLK, N0);                                           \
    HL_LOAD(1, Ahg, Alg, Bhg, Blg, ROWBLK, N0);                                           \
    const int a_row = w * 16 + (L & 15);                                                  \
    const int a_cx  = ((L >> 4) & 1) * 16;                                                \
    const int b_rb  = (L & 7) + ((L >> 4) & 1) * 8;                                       \
    const int b_cx  = ((L >> 3) & 1) * 16;                                                \
    _Pragma("unroll 1")                                                                   \
    for (int kt = 0; kt < 8; kt++) {                                                      \
        if (kt < 7) asm volatile("cp.async.wait_group 1;" ::: "memory");                  \
        else        asm volatile("cp.async.wait_group 0;" ::: "memory");                  \
        __syncthreads();                                                                  \
        if (kt + 2 < 8) HL_LOAD(kt + 2, Ahg, Alg, Bhg, Blg, ROWBLK, N0);                  \
        const uint32_t sb_ = sbase + (uint32_t)(kt % 3) * HL_STAGE;                       \
        _Pragma("unroll")                                                                 \
        for (int ks = 0; ks < 4; ks++) {                                                  \
            uint32_t ah[4], al[4];                                                        \
            uint32_t oa = (uint32_t)(a_row * 128 + ks * 32 + a_cx) ^ ((uint32_t)(a_row & 7) << 4); \
            ldx4(ah, sb_ + oa);                                                           \
            ldx4(al, sb_ + 16384 + oa);                                                   \
            uint32_t bh[4][4], bl[4][4];                                                  \
            _Pragma("unroll")                                                             \
            for (int p = 0; p < 4; p++) {                                                 \
                const int rn = b_rb + p * 16;                                             \
                uint32_t ob_ = (uint32_t)(rn * 128 + ks * 32 + b_cx) ^ ((uint32_t)(rn & 7) << 4); \
                ldx4(bh[p], sb_ + 32768 + ob_);                                           \
                ldx4(bl[p], sb_ + 40960 + ob_);                                           \
            }                                                                             \
            _Pragma("unroll")                                                             \
            for (int nt = 0; nt < 8; nt++) {                                              \
                const int p = nt >> 1, pi = (nt & 1) * 2;                                 \
                mma16816(acc[nt], ah, bh[p][pi], bh[p][pi + 1]);                          \
                mma16816(acc[nt], ah, bl[p][pi], bl[p][pi + 1]);                          \
                mma16816(acc[nt], al, bh[p][pi], bh[p][pi + 1]);                          \
            }                                                                             \
        }                                                                                 \
    }

// ================= gemm_a_mma: A = xp@Wq^T + bq (64 blk) AND Wc = Wo@Wv (32 blk) =================
__global__ __launch_bounds__(256)
void gemm_a_mma(const __half* __restrict__ xph, const __half* __restrict__ xpl,
                const __half* __restrict__ Wqh, const __half* __restrict__ Wql,
                const float* __restrict__ bq, __half* __restrict__ Ah,
                __half* __restrict__ Al, const __half* __restrict__ Woh,
                const __half* __restrict__ Wol, const __half* __restrict__ WvTh,
                const __half* __restrict__ WvTl, __half* __restrict__ Wch,
                __half* __restrict__ Wcl)
{
    extern __shared__ char smem[];
    const uint32_t sbase = smem_u32(smem);
    const int t = threadIdx.x;
    const int L = t & 31;
    const int w = t >> 5;
    const int isA = (int)blockIdx.x < 64;
    const __half *Ag, *Alg, *Bhg, *Blg;
    int rowblk, n0;
    if (isA) {
        Ag = xph; Alg = xpl; Bhg = Wqh; Blg = Wql;
        rowblk = ((int)blockIdx.x >> 3) * 128; n0 = ((int)blockIdx.x & 7) * 64;
    } else {
        const int l = blockIdx.x - 64;
        Ag = Woh; Alg = Wol; Bhg = WvTh; Blg = WvTl;
        rowblk = (l >> 3) * 128; n0 = (l & 7) * 64;
    }

    float acc[8][4];
#pragma unroll
    for (int i = 0; i < 8; i++)
#pragma unroll
        for (int j = 0; j < 4; j++) acc[i][j] = 0.f;

    HL_MAINLOOP(Ag, Alg, Bhg, Blg, rowblk, n0);

    const int g  = L >> 2;
    const int cq = (L & 3) * 2;
    const int r0v = rowblk + w * 16 + g;
    if (isA) {
#pragma unroll
        for (int nt = 0; nt < 8; nt++) {
            const int col = n0 + nt * 8 + cq;
            const float b0 = __ldg(&bq[col]);
            const float b1 = __ldg(&bq[col + 1]);
            split_store(Ah, Al, (size_t)r0v * Cn + col,       acc[nt][0] + b0, acc[nt][1] + b1);
            split_store(Ah, Al, (size_t)(r0v + 8) * Cn + col, acc[nt][2] + b0, acc[nt][3] + b1);
        }
    } else {
#pragma unroll
        for (int nt = 0; nt < 8; nt++) {
            const int col = n0 + nt * 8 + cq;
            split_store(Wch, Wcl, (size_t)r0v * Cn + col,       acc[nt][0], acc[nt][1]);
            split_store(Wch, Wcl, (size_t)(r0v + 8) * Cn + col, acc[nt][2], acc[nt][3]);
        }
    }
}

// ================= gemm_aqk_mma: Aq|Ak (blk<128) + bqA rowdots (blk>=128) =================
// bqA[r] = (Ah[r]+Al[r]) . bq  (constant-over-m parts drop under softmax over m)
__global__ __launch_bounds__(256)
void gemm_aqk_mma(const __half* __restrict__ Ahg, const __half* __restrict__ Alg,
                  const __half* __restrict__ Wqh, const __half* __restrict__ Wql,
                  const __half* __restrict__ Wkh, const __half* __restrict__ Wkl,
                  const float* __restrict__ bq, float* __restrict__ bqA,
                  __half* __restrict__ Oh, __half* __restrict__ Ol)
{
    if ((int)blockIdx.x >= 128) {
        const int row  = ((int)blockIdx.x - 128) * 8 + (threadIdx.x >> 5);
        const int lane = threadIdx.x & 31;
        const size_t rb = (size_t)row * Cn;
        float s = 0.f;
#pragma unroll
        for (int k = 0; k < 16; k++) {
            const int c = lane + 32 * k;
            s += (__half2float(Ahg[rb + c]) + __half2float(Alg[rb + c])) * __ldg(&bq[c]);
        }
#pragma unroll
        for (int off = 16; off > 0; off >>= 1) s += __shfl_xor_sync(0xffffffffu, s, off);
        if (lane == 0) bqA[row] = s;
        return;
    }
    extern __shared__ char smem[];
    const uint32_t sbase = smem_u32(smem);
    const int l  = blockIdx.x;
    const int bx = l & 15;
    const int isK = bx >= 8;
    const __half* Bh_g = isK ? Wkh : Wqh;
    const __half* Bl_g = isK ? Wkl : Wql;
    const int n0 = (bx & 7) * 64;
    const int rowblk = (l >> 4) * 128;
    const int t = threadIdx.x;
    const int L = t & 31;
    const int w = t >> 5;

    float acc[8][4];
#pragma unroll
    for (int i = 0; i < 8; i++)
#pragma unroll
        for (int j = 0; j < 4; j++) acc[i][j] = 0.f;

    HL_MAINLOOP(Ahg, Alg, Bh_g, Bl_g, rowblk, n0);

    const int g  = L >> 2;
    const int cq = (L & 3) * 2;
    const int joff = isK ? 16 : 0;
    const int r0v = rowblk + w * 16 + g;
    const int r1v = r0v + 8;
    const size_t d0 = ((size_t)(r0v >> 4) * 32 + (r0v & 15) + joff) * Cn + n0;
    const size_t d1 = ((size_t)(r1v >> 4) * 32 + (r1v & 15) + joff) * Cn + n0;
#pragma unroll
    for (int nt = 0; nt < 8; nt++) {
        const int col = nt * 8 + cq;
        split_store(Oh, Ol, d0 + col, acc[nt][0], acc[nt][1]);
        split_store(Oh, Ol, d1 + col, acc[nt][2], acc[nt][3]);
    }
}

// ================= gemm_afo_mma: AFo = xa@Wc^T + bvo (fp32 out) =================
__global__ __launch_bounds__(256)
void gemm_afo_mma(const __half* __restrict__ xahg, const __half* __restrict__ xalg,
                  const __half* __restrict__ Wch, const __half* __restrict__ Wcl,
                  const float* __restrict__ bvo, float* __restrict__ AFo)
{
    extern __shared__ char smem[];
    const uint32_t sbase = smem_u32(smem);
    const int n0 = blockIdx.x * 64;
    const int rowblk = blockIdx.y * 128;
    const int t = threadIdx.x;
    const int L = t & 31;
    const int w = t >> 5;

    float acc[8][4];
#pragma unroll
    for (int i = 0; i < 8; i++)
#pragma unroll
        for (int j = 0; j < 4; j++) acc[i][j] = 0.f;

    HL_MAINLOOP(xahg, xalg, Wch, Wcl, rowblk, n0);

    const int g  = L >> 2;
    const int cq = (L & 3) * 2;
    const int r0v = rowblk + w * 16 + g;
#pragma unroll
    for (int nt = 0; nt < 8; nt++) {
        const int col = n0 + nt * 8 + cq;
        const float b0 = __ldg(&bvo[col]);
        const float b1 = __ldg(&bvo[col + 1]);
        *(float2*)(AFo + (size_t)r0v * Cn + col)       = make_float2(acc[nt][0] + b0, acc[nt][1] + b1);
        *(float2*)(AFo + (size_t)(r0v + 8) * Cn + col) = make_float2(acc[nt][2] + b0, acc[nt][3] + b1);
    }
}

// ================= logits via mma (3-stage) =================
#define LG_STAGE 24576
#define LG_SMEM (3 * LG_STAGE + 64)

__global__ __launch_bounds__(256)
void logits12_mma(const __half* __restrict__ Xh,
                  const __half* __restrict__ Ah_g, const __half* __restrict__ Al_g,
                  const float* __restrict__ bqA,
                  float* __restrict__ L1, float* __restrict__ L2)
{
    extern __shared__ char smem[];
    const uint32_t sbase = smem_u32(smem);
    const int b = blockIdx.y;
    const int tokblk = blockIdx.x * 128;
    const int t = threadIdx.x;
    const int L = t & 31;
    const int w = t >> 5;

    if (t < 16) ((float*)(smem + 3 * LG_STAGE))[t] = bqA[b * 16 + t];

#define LG_LOAD(I)                                                                        \
    do {                                                                                  \
        const int s_ = (I) % 3; const int k0_ = (I) * 64;                                 \
        const uint32_t sb_ = sbase + s_ * LG_STAGE;                                       \
        {                                                                                 \
            const int row = t >> 1; const int cb = (t & 1) * 4;                           \
            const __half* gh = Xh + ((size_t)(b * Nn + tokblk + row)) * Cn + k0_ + cb * 8;\
            _Pragma("unroll")                                                             \
            for (int j = 0; j < 4; j++) {                                                 \
                uint32_t o = (uint32_t)(row * 128 + (cb + j) * 16) ^ ((uint32_t)(row & 7) << 4); \
                cp_async16(sb_ + o, gh + j * 8);                                          \
            }                                                                             \
        }                                                                                 \
        {                                                                                 \
            const int jr = t >> 3; const int ch = t & 7;                                  \
            uint32_t o = (uint32_t)(jr * 128 + ch * 16) ^ ((uint32_t)(jr & 7) << 4);      \
            cp_async16(sb_ + 16384 + o, Ah_g + ((size_t)(b * 32 + jr)) * Cn + k0_ + ch * 8); \
            cp_async16(sb_ + 20480 + o, Al_g + ((size_t)(b * 32 + jr)) * Cn + k0_ + ch * 8); \
        }                                                                                 \
        asm volatile("cp.async.commit_group;" ::: "memory");                              \
    } while (0)

    float acc[4][4];
#pragma unroll
    for (int i = 0; i < 4; i++)
#pragma unroll
        for (int j = 0; j < 4; j++) acc[i][j] = 0.f;

    LG_LOAD(0);
    LG_LOAD(1);

    const int a_row = w * 16 + (L & 15);
    const int a_cx  = ((L >> 4) & 1) * 16;
    const int b_rb  = (L & 7) + ((L >> 4) & 1) * 8;
    const int b_cx  = ((L >> 3) & 1) * 16;

#pragma unroll 1
    for (int kt = 0; kt < 8; kt++) {
        if (kt < 7) asm volatile("cp.async.wait_group 1;" ::: "memory");
        else        asm volatile("cp.async.wait_group 0;" ::: "memory");
        __syncthreads();
        if (kt + 2 < 8) LG_LOAD(kt + 2);
        const uint32_t sb_ = sbase + (uint32_t)(kt % 3) * LG_STAGE;
#pragma unroll
        for (int ks = 0; ks < 4; ks++) {
            uint32_t ah[4];
            uint32_t oa = (uint32_t)(a_row * 128 + ks * 32 + a_cx) ^ ((uint32_t)(a_row & 7) << 4);
            ldx4(ah, sb_ + oa);
            uint32_t bh[2][4], bl[2][4];
#pragma unroll
            for (int p = 0; p < 2; p++) {
                const int rn = b_rb + p * 16;
                uint32_t ob_ = (uint32_t)(rn * 128 + ks * 32 + b_cx) ^ ((uint32_t)(rn & 7) << 4);
                ldx4(bh[p], sb_ + 16384 + ob_);
                ldx4(bl[p], sb_ + 20480 + ob_);
            }
#pragma unroll
            for (int nt = 0; nt < 4; nt++) {
                const int p = nt >> 1, pi = (nt & 1) * 2;
                mma16816(acc[nt], ah, bh[p][pi], bh[p][pi + 1]);
                mma16816(acc[nt], ah, bl[p][pi], bl[p][pi + 1]);
            }
        }
    }
#undef LG_LOAD

    const int g  = L >> 2;
    const int cq = (L & 3) * 2;
    const float* bqs = (const float*)(smem + 3 * LG_STAGE);
    const int tk0 = tokblk + w * 16 + g;
#pragma unroll
    for (int nt = 0; nt < 4; nt++) {
        const int j0 = nt * 8 + cq;
        if (nt < 2) {
            float2 v0 = make_float2((acc[nt][0] + bqs[j0]) * SCALE, (acc[nt][1] + bqs[j0 + 1]) * SCALE);
            float2 v1 = make_float2((acc[nt][2] + bqs[j0]) * SCALE, (acc[nt][3] + bqs[j0 + 1]) * SCALE);
            *(float2*)(L1 + ((size_t)b * Nn + tk0)     * 16 + j0) = v0;
            *(float2*)(L1 + ((size_t)b * Nn + tk0 + 8) * 16 + j0) = v1;
        } else {
            const int m0 = j0 - 16;
            L2[((size_t)b * 16 + m0)     * Nn + tk0]     = acc[nt][0] * SCALE;
            L2[((size_t)b * 16 + m0 + 1) * Nn + tk0]     = acc[nt][1] * SCALE;
            L2[((size_t)b * 16 + m0)     * Nn + tk0 + 8] = acc[nt][2] * SCALE;
            L2[((size_t)b * 16 + m0 + 1) * Nn + tk0 + 8] = acc[nt][3] * SCALE;
        }
    }
}

// ================= xa via mma (3-stage) =================
#define PS_STRIDE 1040
#define XA_PS 33280
#define XA_XOFF 66560
#define XA_STAGE 8192
#define XA_SMEM (XA_XOFF + 3 * XA_STAGE)

__global__ __launch_bounds__(256)
void xa_mma(const float* __restrict__ L2, const __half* __restrict__ Xh,
            __half* __restrict__ xah, __half* __restrict__ xal)
{
    extern __shared__ char smem[];
    const uint32_t sbase = smem_u32(smem);
    const int b  = blockIdx.y;
    const int c0 = blockIdx.x * 64;
    const int t  = threadIdx.x;
    const int L  = t & 31;
    const int w  = t >> 5;

    __half* psh = (__half*)smem;
    __half* psl = (__half*)(smem + XA_PS);
    for (int mr = w; mr < 16; mr += 8) {
        const float* row = L2 + ((size_t)b * 16 + mr) * Nn;
        float mx = -INFINITY;
#pragma unroll
        for (int i = 0; i < 32; i++) mx = fmaxf(mx, __ldg(row + L + 32 * i));
#pragma unroll
        for (int off = 16; off > 0; off >>= 1)
            mx = fmaxf(mx, __shfl_xor_sync(0xffffffffu, mx, off));
        float sum = 0.f;
#pragma unroll
        for (int i = 0; i < 32; i++) sum += __expf(__ldg(row + L + 32 * i) - mx);
#pragma unroll
        for (int off = 16; off > 0; off >>= 1)
            sum += __shfl_xor_sync(0xffffffffu, sum, off);
        const float inv = 1.0f / sum;
#pragma unroll
        for (int i = 0; i < 32; i++) {
            float e = __expf(__ldg(row + L + 32 * i) - mx) * inv;
            __half h = __float2half(e);
            psh[mr * PS_STRIDE + L + 32 * i] = h;
            psl[mr * PS_STRIDE + L + 32 * i] = __float2half(e - __half2float(h));
        }
    }
    __syncthreads();

#define XA_LOAD(I)                                                                        \
    do {                                                                                  \
        const int s_ = (I) % 3; const int k0_ = (I) * 64;                                 \
        const uint32_t xb_ = sbase + XA_XOFF + s_ * XA_STAGE;                             \
        const int row = t >> 2; const int cb = (t & 3) * 2;                               \
        const __half* gh = Xh + ((size_t)(b * Nn + k0_ + row)) * Cn + c0 + cb * 8;        \
        _Pragma("unroll")                                                                 \
        for (int j = 0; j < 2; j++) {                                                     \
            uint32_t o = (uint32_t)(row * 128 + (cb + j) * 16) ^ ((uint32_t)(row & 7) << 4); \
            cp_async16(xb_ + o, gh + j * 8);                                              \
        }                                                                                 \
        asm volatile("cp.async.commit_group;" ::: "memory");                              \
    } while (0)

    float acc[4] = {0.f, 0.f, 0.f, 0.f};
    XA_LOAD(0);
    XA_LOAD(1);

    const int arow = L & 15;
    const int asel = ((L >> 4) & 1) * 16;
    const int brl  = L & 15;
    const uint32_t ph_b = sbase;
    const uint32_t pl_b = sbase + XA_PS;

#pragma unroll 1
    for (int kt = 0; kt < 16; kt++) {
        if (kt < 15) asm volatile("cp.async.wait_group 1;" ::: "memory");
        else         asm volatile("cp.async.wait_group 0;" ::: "memory");
        __syncthreads();
        if (kt + 2 < 16) XA_LOAD(kt + 2);
        const uint32_t xb_ = sbase + XA_XOFF + (uint32_t)(kt % 3) * XA_STAGE;
#pragma unroll
        for (int ks = 0; ks < 4; ks++) {
            const int kbyte = (kt * 64 + ks * 16) * 2 + asel;
            uint32_t pa[4], pb2[4];
            ldx4(pa,  ph_b + (uint32_t)(arow * (PS_STRIDE * 2) + kbyte));
            ldx4(pb2, pl_b + (uint32_t)(arow * (PS_STRIDE * 2) + kbyte));
            const int r = ks * 16 + brl;
            uint32_t bh[2];
            uint32_t ob_ = (uint32_t)(r * 128 + w * 16) ^ ((uint32_t)(r & 7) << 4);
            ldx2t(bh, xb_ + ob_);
            mma16816(acc, pa,  bh[0], bh[1]);
            mma16816(acc, pb2, bh[0], bh[1]);
        }
    }
#undef XA_LOAD

    const int g  = L >> 2;
    const int cq = (L & 3) * 2;
    const int c  = c0 + w * 8 + cq;
    split_store(xah, xal, ((size_t)b * 16 + g) * Cn + c,     acc[0], acc[1]);
    split_store(xah, xal, ((size_t)b * 16 + g + 8) * Cn + c, acc[2], acc[3]);
}

// ================= final (unchanged) =================
__global__ __launch_bounds__(512)
void final_kernel(const float* __restrict__ L1, const float* __restrict__ AFo,
                  const float* __restrict__ bo, float* __restrict__ out)
{
    __shared__ float4 afo4[Mn * 128];
    __shared__ float  l1s[64 * 16];
    __shared__ float4 bo4[128];
    const int b    = blockIdx.y;
    const int n0   = blockIdx.x * 64;
    const int tid  = threadIdx.x;
    const int warp = tid >> 5;
    const int lane = tid & 31;

    {
        const float4* s = (const float4*)(AFo + (size_t)b * Mn * Cn);
        for (int i = tid; i < 2048; i += 512) afo4[i] = s[i];
        const float4* sl = (const float4*)(L1 + ((size_t)b * Nn + n0) * 16);
        if (tid < 256) ((float4*)l1s)[tid] = sl[tid];
        if (tid < 128) bo4[tid] = ((const float4*)bo)[tid];
    }
    __syncthreads();

#pragma unroll 1
    for (int t = 0; t < 4; t++) {
        const int tok = warp * 4 + t;
        float lg[16];
#pragma unroll
        for (int m = 0; m < Mn; m++) lg[m] = l1s[tok * 16 + m];
        float mx = lg[0];
#pragma unroll
        for (int m = 1; m < Mn; m++) mx = fmaxf(mx, lg[m]);
        float s = 0.f;
#pragma unroll
        for (int m = 0; m < Mn; m++) { lg[m] = __expf(lg[m] - mx); s += lg[m]; }
        const float inv = 1.0f / s;

        float4* orow = (float4*)(out + ((size_t)b * Nn + n0 + tok) * Cn);
#pragma unroll 1
        for (int kc = 0; kc < 4; kc++) {
            const int cidx = kc * 32 + lane;
            float4 acc = make_float4(0.f, 0.f, 0.f, 0.f);
#pragma unroll
            for (int m = 0; m < Mn; m++) {
                float4 f = afo4[m * 128 + cidx];
                acc.x = fmaf(lg[m], f.x, acc.x);
                acc.y = fmaf(lg[m], f.y, acc.y);
                acc.z = fmaf(lg[m], f.z, acc.z);
                acc.w = fmaf(lg[m], f.w, acc.w);
            }
            float4 bb = bo4[cidx];
            acc.x = acc.x * inv + bb.x;
            acc.y = acc.y * inv + bb.y;
            acc.z = acc.z * inv + bb.z;
            acc.w = acc.w * inv + bb.w;
            orow[cidx] = acc;
        }
    }
}

// ================= launch =================
extern "C" void kernel_launch(void* const* d_in, const int* in_sizes, int n_in,
                              void* d_out, int out_size)
{
    const float* x  = (const float*)d_in[0];
    const float* Wq = (const float*)d_in[1];
    const float* bq = (const float*)d_in[2];
    const float* Wk = (const float*)d_in[3];
    const float* Wv = (const float*)d_in[5];
    const float* bv = (const float*)d_in[6];
    const float* Wo = (const float*)d_in[7];
    const float* bo = (const float*)d_in[8];
    float* out = (float*)d_out;

    float *bqA, *bvo, *L1, *L2, *AFo;
    __half *xh, *xph, *xpl, *aqkh, *aqkl;
    __half *WqTh, *WqTl, *WkTh, *WkTl, *WvTh, *WvTl, *Wqh, *Wql, *Woh, *Wol;
    __half *Ah, *Al, *Wch, *Wcl, *xah, *xal;
    cudaGetSymbolAddress((void**)&bqA,  g_bqA);
    cudaGetSymbolAddress((void**)&bvo,  g_bvo);
    cudaGetSymbolAddress((void**)&L1,   g_L1);
    cudaGetSymbolAddress((void**)&L2,   g_L2);
    cudaGetSymbolAddress((void**)&AFo,  g_AFo);
    cudaGetSymbolAddress((void**)&xh,   g_xh);
    cudaGetSymbolAddress((void**)&xph,  g_xph);
    cudaGetSymbolAddress((void**)&xpl,  g_xpl);
    cudaGetSymbolAddress((void**)&aqkh, g_aqkh);
    cudaGetSymbolAddress((void**)&aqkl, g_aqkl);
    cudaGetSymbolAddress((void**)&WqTh, g_WqTh);
    cudaGetSymbolAddress((void**)&WqTl, g_WqTl);
    cudaGetSymbolAddress((void**)&WkTh, g_WkTh);
    cudaGetSymbolAddress((void**)&WkTl, g_WkTl);
    cudaGetSymbolAddress((void**)&WvTh, g_WvTh);
    cudaGetSymbolAddress((void**)&WvTl, g_WvTl);
    cudaGetSymbolAddress((void**)&Wqh,  g_Wqh);
    cudaGetSymbolAddress((void**)&Wql,  g_Wql);
    cudaGetSymbolAddress((void**)&Woh,  g_Woh);
    cudaGetSymbolAddress((void**)&Wol,  g_Wol);
    cudaGetSymbolAddress((void**)&Ah,   g_Ah);
    cudaGetSymbolAddress((void**)&Al,   g_Al);
    cudaGetSymbolAddress((void**)&Wch,  g_Wch);
    cudaGetSymbolAddress((void**)&Wcl,  g_Wcl);
    cudaGetSymbolAddress((void**)&xah,  g_xah);
    cudaGetSymbolAddress((void**)&xal,  g_xal);

    static int attr_set = 0;
    if (!attr_set) {
        cudaFuncSetAttribute(gemm_a_mma,   cudaFuncAttributeMaxDynamicSharedMemorySize, HL_SMEM);
        cudaFuncSetAttribute(gemm_aqk_mma, cudaFuncAttributeMaxDynamicSharedMemorySize, HL_SMEM);
        cudaFuncSetAttribute(gemm_afo_mma, cudaFuncAttributeMaxDynamicSharedMemorySize, HL_SMEM);
        cudaFuncSetAttribute(logits12_mma, cudaFuncAttributeMaxDynamicSharedMemorySize, LG_SMEM);
        cudaFuncSetAttribute(xa_mma,       cudaFuncAttributeMaxDynamicSharedMemorySize, XA_SMEM);
        attr_set = 1;
    }

    // 1. merged prep + split (independent work, one launch)
    prep_split_kernel<<<2304, 512>>>(x, Wq, Wk, Wv, Wo, bv,
                                     xh, xph, xpl,
                                     WqTh, WqTl, WkTh, WkTl, WvTh, WvTl,
                                     Wqh, Wql, Woh, Wol, bvo);
    // 2. A = xp@Wq^T + bq AND Wc = Wo@Wv
    gemm_a_mma<<<96, 256, HL_SMEM>>>(xph, xpl, Wqh, Wql, bq, Ah, Al,
                                     Woh, Wol, WvTh, WvTl, Wch, Wcl);
    // 3. Aq|Ak via mma + bqA rowdots
    gemm_aqk_mma<<<256, 256, HL_SMEM>>>(Ah, Al, WqTh, WqTl, WkTh, WkTl, bq, bqA, aqkh, aqkl);
    // 4-5. logits + xa
    logits12_mma<<<dim3(8, 64), 256, LG_SMEM>>>(xh, aqkh, aqkl, bqA, L1, L2);
    xa_mma<<<dim3(8, 64), 256, XA_SMEM>>>(L2, xh, xah, xal);
    // 6. AFo via mma
    gemm_afo_mma<<<dim3(8, 8), 256, HL_SMEM>>>(xah, xal, Wch, Wcl, bvo, AFo);
    // 7. final combine
    final_kernel<<<dim3(16, 64), 512>>>(L1, AFo, bo, out);
}